// round 5
// baseline (speedup 1.0000x reference)
#include <cuda_runtime.h>
#include <cuda_bf16.h>

// Problem constants: P=Q=3, M=N=127, DIM=3, SU=SV=256, B=16
#define PB    16
#define PDEG  3
#define PM    127
#define PL    132          // knot vector length
#define PS    256          // samples per direction
#define PNC   128          // control points per direction
#define PDIM  3
#define PEPS  1e-8f
#define RG    4            // rows per thread in rowsum kernel
#define TUC   8            // u's per block in ucontract kernel
#define SROWS 11           // staged R rows (44KB shared)

// ---- device scratch (allocation-free) ----
__device__ float4 g_R[PB][PNC][PS];     // 8 MB rowsum scratch (L2-resident)
__device__ float4 g_nu4[PB][PS];        // u basis weights
__device__ int    g_iu[PB][PS];         // u window start (span - 3)

// ---------------------------------------------------------------------------
// normalize knots into sK (cumsum + rescale); block-collective.
// ---------------------------------------------------------------------------
__device__ __forceinline__ void knots_to_sK(const float* __restrict__ knots,
                                            float* sK, int tid)
{
    if (tid < PL) {
        float x = knots[tid];
        sK[tid] = (x < 0.0f) ? 0.0001f : x;
    }
    __syncthreads();

    if (tid < 32) {
        const int CH = 5;
        const int base = tid * CH;
        float vch[CH];
        float run = 0.0f;
        #pragma unroll
        for (int k = 0; k < CH; k++) {
            int i = base + k;
            float x = (i < PL) ? sK[i] : 0.0f;
            run += x;
            vch[k] = run;
        }
        float incl = run;
        #pragma unroll
        for (int off = 1; off < 32; off <<= 1) {
            float nb = __shfl_up_sync(0xffffffffu, incl, off);
            if (tid >= off) incl += nb;
        }
        float excl = incl - run;
        #pragma unroll
        for (int k = 0; k < CH; k++) {
            int i = base + k;
            if (i < PL) sK[i] = excl + vch[k];
        }
    }
    __syncthreads();

    const float k0  = sK[0];
    const float inv = 1.0f / (sK[PL - 1] - k0);
    __syncthreads();
    if (tid < PL) sK[tid] = (sK[tid] - k0) * inv;
    __syncthreads();
}

// span find (binary search + tie-walk, argmin semantics) + Cox-de Boor deg 3
__device__ __forceinline__ int basis_at(const float* sK, float t, float* Ni)
{
    int j;
    {
        const int cnt = PL - 2 * PDEG;          // 126
        int lo = 0, hi = cnt;
        while (lo < hi) {
            int mid = (lo + hi) >> 1;
            if (t - sK[PDEG + mid] > PEPS) lo = mid + 1;
            else hi = mid;
        }
        j = lo - 1;
        if (j < 0) j = 0;
        else {
            while (j > 0 && sK[PDEG + j - 1] == sK[PDEG + j]) j--;
        }
    }
    int span = j + PDEG;
    if (span < PDEG) span = PDEG;
    if (span > PM)   span = PM;

    Ni[0] = 1.0f; Ni[1] = 0.0f; Ni[2] = 0.0f; Ni[3] = 0.0f;
    #pragma unroll
    for (int k = 1; k <= PDEG; k++) {
        float saved = 0.0f;
        #pragma unroll
        for (int r = 0; r < PDEG; r++) {
            if (r >= k) break;
            float K1 = sK[span + r + 1];
            float K2 = sK[span + 1 - k + r];
            float denom = (K1 - t) + (t - K2);
            float temp = (denom == 0.0f) ? 0.0001f : __fdividef(Ni[r], denom);
            Ni[r] = saved + (K1 - t) * temp;
            saved = (t - K2) * temp;
        }
        Ni[k] = saved;
    }
    return span;
}

// ---------------------------------------------------------------------------
// Kernel 1: fused v-basis + rowsums (+ u-basis tables on rchunk==0 blocks).
// grid = B * (PNC/RG) = 512 blocks, blockDim = 256 (thread = vv).
// ---------------------------------------------------------------------------
__global__ void __launch_bounds__(PS)
surf_rowsum_kernel(const float* __restrict__ ctrl,
                   const float* __restrict__ knot_u,
                   const float* __restrict__ knot_v,
                   const float* __restrict__ u,
                   const float* __restrict__ v)
{
    const int b      = blockIdx.x / (PNC / RG);
    const int rchunk = blockIdx.x % (PNC / RG);
    const int rbase  = rchunk * RG;
    const int vv     = threadIdx.x;

    __shared__ float sK[PL];
    knots_to_sK(knot_v + b * PL, sK, threadIdx.x);

    float nv[PDEG + 1];
    const int span = basis_at(sK, v[vv], nv);
    const int iv = span - PDEG;

    // blocks with rchunk==0 additionally produce the u-basis tables
    // (all 256 threads in parallel, one u-sample each; reuses sK buffer).
    if (rchunk == 0) {
        __syncthreads();                       // everyone done reading v-knots
        knots_to_sK(knot_u + b * PL, sK, threadIdx.x);
        float nu[PDEG + 1];
        const int uspan = basis_at(sK, u[threadIdx.x], nu);
        g_iu[b][threadIdx.x]  = uspan - PDEG;
        g_nu4[b][threadIdx.x] = make_float4(nu[0], nu[1], nu[2], nu[3]);
    }

    const float* base = ctrl + (((long)b * PNC) * PNC + iv) * PDIM;

    #pragma unroll
    for (int j = 0; j < RG; j++) {
        const float* row = base + (long)(rbase + j) * (PNC * PDIM);
        float s0 = 0.0f, s1 = 0.0f, s2 = 0.0f;
        #pragma unroll
        for (int q = 0; q <= PDEG; q++) {
            const float w = nv[q];
            s0 = fmaf(w, __ldg(row + q * PDIM + 0), s0);
            s1 = fmaf(w, __ldg(row + q * PDIM + 1), s1);
            s2 = fmaf(w, __ldg(row + q * PDIM + 2), s2);
        }
        g_R[b][rbase + j][vv] = make_float4(s0, s1, s2, 0.0f);
    }
}

// ---------------------------------------------------------------------------
// Kernel 2: u-contraction, TUC u's per block, R rows staged in shared.
// out[b][uu][vv] = sum_p nu[uu][p] * R[b][iu[uu]+p][vv]
// grid = B * (PS/TUC) = 512 blocks, blockDim = 256 (thread = vv).
// ---------------------------------------------------------------------------
__global__ void __launch_bounds__(PS)
surf_ucontract_kernel(float* __restrict__ out)
{
    const int b  = blockIdx.x / (PS / TUC);
    const int u0 = (blockIdx.x % (PS / TUC)) * TUC;
    const int vv = threadIdx.x;

    __shared__ float4 sR[SROWS][PS];

    // u tables (broadcast loads, uniform per block)
    int    iu[TUC];
    float4 nu[TUC];
    #pragma unroll
    for (int i = 0; i < TUC; i++) {
        iu[i] = g_iu[b][u0 + i];
        nu[i] = g_nu4[b][u0 + i];
    }
    const int r0 = iu[0];                       // spans are non-decreasing
    const int r1 = iu[TUC - 1] + PDEG;
    const int nrows = r1 - r0 + 1;

    float4 res[TUC];

    if (nrows <= SROWS) {                       // uniform branch per block
        for (int j = 0; j < nrows; j++)
            sR[j][vv] = g_R[b][r0 + j][vv];
        __syncthreads();

        #pragma unroll
        for (int i = 0; i < TUC; i++) {
            const int o = iu[i] - r0;
            float4 r0v = sR[o + 0][vv];
            float4 r1v = sR[o + 1][vv];
            float4 r2v = sR[o + 2][vv];
            float4 r3v = sR[o + 3][vv];
            float a0, a1, a2;
            a0 = nu[i].x * r0v.x; a1 = nu[i].x * r0v.y; a2 = nu[i].x * r0v.z;
            a0 = fmaf(nu[i].y, r1v.x, a0); a1 = fmaf(nu[i].y, r1v.y, a1); a2 = fmaf(nu[i].y, r1v.z, a2);
            a0 = fmaf(nu[i].z, r2v.x, a0); a1 = fmaf(nu[i].z, r2v.y, a1); a2 = fmaf(nu[i].z, r2v.z, a2);
            a0 = fmaf(nu[i].w, r3v.x, a0); a1 = fmaf(nu[i].w, r3v.y, a1); a2 = fmaf(nu[i].w, r3v.z, a2);
            res[i] = make_float4(a0, a1, a2, 0.0f);
        }
    } else {                                    // rare wide-span fallback
        #pragma unroll
        for (int i = 0; i < TUC; i++) {
            float4 r0v = __ldg(&g_R[b][iu[i] + 0][vv]);
            float4 r1v = __ldg(&g_R[b][iu[i] + 1][vv]);
            float4 r2v = __ldg(&g_R[b][iu[i] + 2][vv]);
            float4 r3v = __ldg(&g_R[b][iu[i] + 3][vv]);
            float a0, a1, a2;
            a0 = nu[i].x * r0v.x; a1 = nu[i].x * r0v.y; a2 = nu[i].x * r0v.z;
            a0 = fmaf(nu[i].y, r1v.x, a0); a1 = fmaf(nu[i].y, r1v.y, a1); a2 = fmaf(nu[i].y, r1v.z, a2);
            a0 = fmaf(nu[i].z, r2v.x, a0); a1 = fmaf(nu[i].z, r2v.y, a1); a2 = fmaf(nu[i].z, r2v.z, a2);
            a0 = fmaf(nu[i].w, r3v.x, a0); a1 = fmaf(nu[i].w, r3v.y, a1); a2 = fmaf(nu[i].w, r3v.z, a2);
            res[i] = make_float4(a0, a1, a2, 0.0f);
        }
    }

    #pragma unroll
    for (int i = 0; i < TUC; i++) {
        float* o = out + (((long)b * PS + (u0 + i)) * PS + vv) * PDIM;
        o[0] = res[i].x;
        o[1] = res[i].y;
        o[2] = res[i].z;
    }
}

// ---------------------------------------------------------------------------
extern "C" void kernel_launch(void* const* d_in, const int* in_sizes, int n_in,
                              void* d_out, int out_size)
{
    const float* ctrl   = (const float*)d_in[0];  // (B, 128, 128, 3)
    const float* knot_u = (const float*)d_in[1];  // (B, 132)
    const float* knot_v = (const float*)d_in[2];  // (B, 132)
    const float* u      = (const float*)d_in[3];  // (256,)
    const float* v      = (const float*)d_in[4];  // (256,)
    float* out = (float*)d_out;                   // (B, 256, 256, 3)

    surf_rowsum_kernel<<<PB * (PNC / RG), PS>>>(ctrl, knot_u, knot_v, u, v);
    surf_ucontract_kernel<<<PB * (PS / TUC), PS>>>(out);
}

// round 6
// speedup vs baseline: 1.0956x; 1.0956x over previous
#include <cuda_runtime.h>
#include <cuda_bf16.h>

// Problem constants: P=Q=3, M=N=127, DIM=3, SU=SV=256, B=16
#define PB    16
#define PDEG  3
#define PM    127
#define PL    132          // knot vector length
#define PS    256          // samples per direction
#define PNC   128          // control points per direction
#define PDIM  3
#define PEPS  1e-8f
#define TUC   8            // u's per block
#define SROWS 11           // staged rowsum rows in shared (44KB)

// ---------------------------------------------------------------------------
// normalize knots into sK (cumsum + rescale); block-collective.
// ---------------------------------------------------------------------------
__device__ __forceinline__ void knots_to_sK(const float* __restrict__ knots,
                                            float* sK, int tid)
{
    if (tid < PL) {
        float x = knots[tid];
        sK[tid] = (x < 0.0f) ? 0.0001f : x;
    }
    __syncthreads();

    if (tid < 32) {
        const int CH = 5;                       // 32*5 >= 132
        const int base = tid * CH;
        float vch[CH];
        float run = 0.0f;
        #pragma unroll
        for (int k = 0; k < CH; k++) {
            int i = base + k;
            float x = (i < PL) ? sK[i] : 0.0f;
            run += x;
            vch[k] = run;
        }
        float incl = run;
        #pragma unroll
        for (int off = 1; off < 32; off <<= 1) {
            float nb = __shfl_up_sync(0xffffffffu, incl, off);
            if (tid >= off) incl += nb;
        }
        float excl = incl - run;
        #pragma unroll
        for (int k = 0; k < CH; k++) {
            int i = base + k;
            if (i < PL) sK[i] = excl + vch[k];
        }
    }
    __syncthreads();

    const float k0  = sK[0];
    const float inv = 1.0f / (sK[PL - 1] - k0);
    __syncthreads();
    if (tid < PL) sK[tid] = (sK[tid] - k0) * inv;
    __syncthreads();
}

// span find (binary search + tie-walk, argmin semantics) + Cox-de Boor deg 3
__device__ __forceinline__ int basis_at(const float* sK, float t, float* Ni)
{
    int j;
    {
        const int cnt = PL - 2 * PDEG;          // 126
        int lo = 0, hi = cnt;
        while (lo < hi) {
            int mid = (lo + hi) >> 1;
            if (t - sK[PDEG + mid] > PEPS) lo = mid + 1;
            else hi = mid;
        }
        j = lo - 1;
        if (j < 0) j = 0;
        else {
            while (j > 0 && sK[PDEG + j - 1] == sK[PDEG + j]) j--;
        }
    }
    int span = j + PDEG;
    if (span < PDEG) span = PDEG;
    if (span > PM)   span = PM;

    Ni[0] = 1.0f; Ni[1] = 0.0f; Ni[2] = 0.0f; Ni[3] = 0.0f;
    #pragma unroll
    for (int k = 1; k <= PDEG; k++) {
        float saved = 0.0f;
        #pragma unroll
        for (int r = 0; r < PDEG; r++) {
            if (r >= k) break;
            float K1 = sK[span + r + 1];
            float K2 = sK[span + 1 - k + r];
            float denom = (K1 - t) + (t - K2);
            float temp = (denom == 0.0f) ? 0.0001f : __fdividef(Ni[r], denom);
            Ni[r] = saved + (K1 - t) * temp;
            saved = (t - K2) * temp;
        }
        Ni[k] = saved;
    }
    return span;
}

// ---------------------------------------------------------------------------
// Fully fused kernel: basis + rowsums (in shared) + u-contraction + store.
// grid = B * (PS/TUC) = 512 blocks, blockDim = 256 (thread = vv).
// ---------------------------------------------------------------------------
__global__ void __launch_bounds__(PS)
surf_fused_kernel(const float* __restrict__ ctrl,
                  const float* __restrict__ knot_u,
                  const float* __restrict__ knot_v,
                  const float* __restrict__ u,
                  const float* __restrict__ v,
                  float* __restrict__ out)
{
    const int b  = blockIdx.x / (PS / TUC);
    const int u0 = (blockIdx.x % (PS / TUC)) * TUC;
    const int vv = threadIdx.x;
    const int tid = threadIdx.x;

    __shared__ float  sKv[PL];
    __shared__ float  sKu[PL];
    __shared__ int    s_iu[TUC];
    __shared__ float4 s_nu[TUC];
    __shared__ float4 sR[SROWS][PS];

    knots_to_sK(knot_v + b * PL, sKv, tid);
    knots_to_sK(knot_u + b * PL, sKu, tid);

    // v-basis: every thread, its own sample (parallel)
    float nv[PDEG + 1];
    const int iv = basis_at(sKv, v[vv], nv) - PDEG;

    // u-basis: 8 threads, one u-sample each (parallel chain, others wait)
    if (tid < TUC) {
        float nu[PDEG + 1];
        const int us = basis_at(sKu, u[u0 + tid], nu);
        s_iu[tid] = us - PDEG;
        s_nu[tid] = make_float4(nu[0], nu[1], nu[2], nu[3]);
    }
    __syncthreads();

    const float* cbase = ctrl + (((long)b * PNC) * PNC + iv) * PDIM;

    // grouped-window loop (block-uniform; typically a single iteration)
    int done = 0;
    while (done < TUC) {
        const int rlo = s_iu[done];
        int gend = done;
        while (gend + 1 < TUC && s_iu[gend + 1] + PDEG - rlo < SROWS) gend++;
        const int nrows = s_iu[gend] + PDEG - rlo + 1;   // <= SROWS

        // compute rowsums for rows [rlo, rlo+nrows) into shared
        for (int j = 0; j < nrows; j++) {
            const float* row = cbase + (long)(rlo + j) * (PNC * PDIM);
            float s0 = 0.0f, s1 = 0.0f, s2 = 0.0f;
            #pragma unroll
            for (int q = 0; q <= PDEG; q++) {
                const float w = nv[q];
                s0 = fmaf(w, __ldg(row + q * PDIM + 0), s0);
                s1 = fmaf(w, __ldg(row + q * PDIM + 1), s1);
                s2 = fmaf(w, __ldg(row + q * PDIM + 2), s2);
            }
            sR[j][vv] = make_float4(s0, s1, s2, 0.0f);
        }
        __syncthreads();

        // contract each u in the group
        for (int i = done; i <= gend; i++) {
            const int o = s_iu[i] - rlo;
            const float4 w = s_nu[i];
            float4 r0 = sR[o + 0][vv];
            float4 r1 = sR[o + 1][vv];
            float4 r2 = sR[o + 2][vv];
            float4 r3 = sR[o + 3][vv];
            float a0, a1, a2;
            a0 = w.x * r0.x;            a1 = w.x * r0.y;            a2 = w.x * r0.z;
            a0 = fmaf(w.y, r1.x, a0);   a1 = fmaf(w.y, r1.y, a1);   a2 = fmaf(w.y, r1.z, a2);
            a0 = fmaf(w.z, r2.x, a0);   a1 = fmaf(w.z, r2.y, a1);   a2 = fmaf(w.z, r2.z, a2);
            a0 = fmaf(w.w, r3.x, a0);   a1 = fmaf(w.w, r3.y, a1);   a2 = fmaf(w.w, r3.z, a2);

            float* o_ptr = out + (((long)b * PS + (u0 + i)) * PS + vv) * PDIM;
            o_ptr[0] = a0;
            o_ptr[1] = a1;
            o_ptr[2] = a2;
        }

        done = gend + 1;
        if (done < TUC) __syncthreads();   // protect sR before re-staging
    }
}

// ---------------------------------------------------------------------------
extern "C" void kernel_launch(void* const* d_in, const int* in_sizes, int n_in,
                              void* d_out, int out_size)
{
    const float* ctrl   = (const float*)d_in[0];  // (B, 128, 128, 3)
    const float* knot_u = (const float*)d_in[1];  // (B, 132)
    const float* knot_v = (const float*)d_in[2];  // (B, 132)
    const float* u      = (const float*)d_in[3];  // (256,)
    const float* v      = (const float*)d_in[4];  // (256,)
    float* out = (float*)d_out;                   // (B, 256, 256, 3)

    surf_fused_kernel<<<PB * (PS / TUC), PS>>>(ctrl, knot_u, knot_v, u, v, out);
}

// round 11
// speedup vs baseline: 1.1896x; 1.0858x over previous
#include <cuda_runtime.h>
#include <cuda_bf16.h>

// Problem constants: P=Q=3, M=N=127, DIM=3, SU=SV=256, B=16
#define PB    16
#define PDEG  3
#define PM    127
#define PL    132          // knot vector length
#define PS    256          // samples per direction
#define PNC   128          // control points per direction
#define PDIM  3
#define PEPS  1e-8f
#define TUC   8            // u's per block
#define SROWS 11           // staged ctrl rows in shared
#define ROWF  (PNC * PDIM) // floats per ctrl row (384)
#define ROWV4 (ROWF / 4)   // float4 per ctrl row (96)

// ---------------------------------------------------------------------------
// One warp normalizes one knot vector entirely in registers, writes sK.
// cumsum order matches jnp.cumsum (sequential within chunk, chunks in order).
// ---------------------------------------------------------------------------
__device__ __forceinline__ void warp_scan_knots(const float* __restrict__ knots,
                                                float* __restrict__ sK)
{
    const int lane = threadIdx.x & 31;
    const int CH = 5;                           // 32*5 >= 132
    const int base = lane * CH;
    float vch[CH];
    float run = 0.0f;
    #pragma unroll
    for (int k = 0; k < CH; k++) {
        int i = base + k;
        float x = 0.0f;
        if (i < PL) {
            x = knots[i];
            if (x < 0.0f) x = 0.0001f;
        }
        run += x;
        vch[k] = run;
    }
    float incl = run;
    #pragma unroll
    for (int off = 1; off < 32; off <<= 1) {
        float nb = __shfl_up_sync(0xffffffffu, incl, off);
        if (lane >= off) incl += nb;
    }
    const float excl = incl - run;
    const float sc0  = excl + vch[0];
    const float k0   = __shfl_sync(0xffffffffu, sc0, 0);
    const float last = __shfl_sync(0xffffffffu, incl, 31);   // == cumsum[131]
    const float inv  = 1.0f / (last - k0);
    #pragma unroll
    for (int k = 0; k < CH; k++) {
        int i = base + k;
        if (i < PL) sK[i] = ((excl + vch[k]) - k0) * inv;
    }
}

// span find (binary search + tie-walk, argmin semantics) + Cox-de Boor deg 3
__device__ __forceinline__ int basis_at(const float* sK, float t, float* Ni)
{
    int j;
    {
        const int cnt = PL - 2 * PDEG;          // 126
        int lo = 0, hi = cnt;
        while (lo < hi) {
            int mid = (lo + hi) >> 1;
            if (t - sK[PDEG + mid] > PEPS) lo = mid + 1;
            else hi = mid;
        }
        j = lo - 1;
        if (j < 0) j = 0;
        else {
            while (j > 0 && sK[PDEG + j - 1] == sK[PDEG + j]) j--;
        }
    }
    int span = j + PDEG;
    if (span < PDEG) span = PDEG;
    if (span > PM)   span = PM;

    Ni[0] = 1.0f; Ni[1] = 0.0f; Ni[2] = 0.0f; Ni[3] = 0.0f;
    #pragma unroll
    for (int k = 1; k <= PDEG; k++) {
        float saved = 0.0f;
        #pragma unroll
        for (int r = 0; r < PDEG; r++) {
            if (r >= k) break;
            float K1 = sK[span + r + 1];
            float K2 = sK[span + 1 - k + r];
            float denom = (K1 - t) + (t - K2);
            float temp = (denom == 0.0f) ? 0.0001f : __fdividef(Ni[r], denom);
            Ni[r] = saved + (K1 - t) * temp;
            saved = (t - K2) * temp;
        }
        Ni[k] = saved;
    }
    return span;
}

// ---------------------------------------------------------------------------
// Fused kernel: basis + coalesced ctrl staging + v-contract + u-fanout.
// grid = B * (PS/TUC) = 512 blocks, blockDim = 256 (thread = vv).
// ---------------------------------------------------------------------------
__global__ void __launch_bounds__(PS)
surf_fused_kernel(const float* __restrict__ ctrl,
                  const float* __restrict__ knot_u,
                  const float* __restrict__ knot_v,
                  const float* __restrict__ u,
                  const float* __restrict__ v,
                  float* __restrict__ out)
{
    const int b   = blockIdx.x / (PS / TUC);
    const int u0  = (blockIdx.x % (PS / TUC)) * TUC;
    const int vv  = threadIdx.x;
    const int tid = threadIdx.x;
    const int wid = tid >> 5;

    __shared__ float sKv[PL];
    __shared__ float sKu[PL];
    __shared__ int   s_iu[TUC];
    __shared__ float s_nu[TUC][PDEG + 1];
    __shared__ float s_w[SROWS][TUC];
    __shared__ float sC[SROWS * ROWF];          // staged ctrl rows (16.9 KB)

    // parallel knot normalization: warp 0 -> v, warp 1 -> u
    if (wid == 0) warp_scan_knots(knot_v + b * PL, sKv);
    else if (wid == 1) warp_scan_knots(knot_u + b * PL, sKu);
    __syncthreads();

    // v-basis: every thread its own sample (parallel)
    float nv0, nv1, nv2, nv3;
    int iv;
    {
        float nv[PDEG + 1];
        iv = basis_at(sKv, v[vv], nv) - PDEG;
        nv0 = nv[0]; nv1 = nv[1]; nv2 = nv[2]; nv3 = nv[3];
    }

    // u-basis: 8 threads, one u each
    if (tid < TUC) {
        float nu[PDEG + 1];
        const int us = basis_at(sKu, u[u0 + tid], nu);
        s_iu[tid] = us - PDEG;
        #pragma unroll
        for (int p = 0; p <= PDEG; p++) s_nu[tid][p] = nu[p];
    }
    __syncthreads();

    const float4* cb4 = (const float4*)(ctrl + (long)b * PNC * ROWF);

    float acc[TUC][PDIM];
    #pragma unroll
    for (int i = 0; i < TUC; i++) {
        acc[i][0] = 0.0f; acc[i][1] = 0.0f; acc[i][2] = 0.0f;
    }

    // grouped-window loop (block-uniform; typically one iteration)
    int done = 0;
    while (done < TUC) {
        const int rlo = s_iu[done];
        int gend = done;
        while (gend + 1 < TUC && s_iu[gend + 1] + PDEG - rlo < SROWS) gend++;
        const int nrows = s_iu[gend] + PDEG - rlo + 1;   // <= SROWS

        __syncthreads();   // prior iteration's reads of s_w/sC complete

        // weight table: w = Nu if u i (within this group) covers row, else 0
        if (tid < SROWS * TUC) {
            const int j = tid / TUC, i = tid % TUC;
            float w = 0.0f;
            if (j < nrows && i >= done && i <= gend) {
                const int p = (rlo + j) - s_iu[i];
                if (p >= 0 && p <= PDEG) w = s_nu[i][p];
            }
            s_w[j][i] = w;
        }

        // coalesced staging of ctrl rows [rlo, rlo+nrows)
        for (int idx = tid; idx < nrows * ROWV4; idx += PS) {
            const int j = idx / ROWV4, t = idx % ROWV4;
            ((float4*)sC)[j * ROWV4 + t] = cb4[(long)(rlo + j) * ROWV4 + t];
        }
        __syncthreads();

        // main loop: per row, v-contract from shared + u-fanout to registers
        for (int j = 0; j < nrows; j++) {
            const float* f = sC + j * ROWF + iv * PDIM;
            const float r0 = fmaf(nv0, f[0], fmaf(nv1, f[3], fmaf(nv2, f[6],  nv3 * f[9])));
            const float r1 = fmaf(nv0, f[1], fmaf(nv1, f[4], fmaf(nv2, f[7],  nv3 * f[10])));
            const float r2 = fmaf(nv0, f[2], fmaf(nv1, f[5], fmaf(nv2, f[8],  nv3 * f[11])));
            #pragma unroll
            for (int i = 0; i < TUC; i++) {
                const float w = s_w[j][i];      // broadcast LDS
                acc[i][0] = fmaf(w, r0, acc[i][0]);
                acc[i][1] = fmaf(w, r1, acc[i][1]);
                acc[i][2] = fmaf(w, r2, acc[i][2]);
            }
        }

        done = gend + 1;
    }

    #pragma unroll
    for (int i = 0; i < TUC; i++) {
        float* o = out + (((long)b * PS + (u0 + i)) * PS + vv) * PDIM;
        o[0] = acc[i][0];
        o[1] = acc[i][1];
        o[2] = acc[i][2];
    }
}

// ---------------------------------------------------------------------------
extern "C" void kernel_launch(void* const* d_in, const int* in_sizes, int n_in,
                              void* d_out, int out_size)
{
    const float* ctrl   = (const float*)d_in[0];  // (B, 128, 128, 3)
    const float* knot_u = (const float*)d_in[1];  // (B, 132)
    const float* knot_v = (const float*)d_in[2];  // (B, 132)
    const float* u      = (const float*)d_in[3];  // (256,)
    const float* v      = (const float*)d_in[4];  // (256,)
    float* out = (float*)d_out;                   // (B, 256, 256, 3)

    surf_fused_kernel<<<PB * (PS / TUC), PS>>>(ctrl, knot_u, knot_v, u, v, out);
}